// round 12
// baseline (speedup 1.0000x reference)
#include <cuda_runtime.h>
#include <cstdint>

#define B 256
#define S 2048
#define V 100000
#define E 128

#define PBLK 592                 // 4 resident blocks/SM x 148 SMs
#define NWARPS (PBLK * 8)        // 4736 streaming warps
#define NJOBS (V / 8)            // 12500 8-row jobs (V % 8 == 0)

// __device__ scratch (no cudaMalloc allowed). Zero-initialized at load.
__device__ float g_proj[V];          // proj[v] = dot(emb[v], fc_w)
__device__ float g_part[B * 2];      // 2 partials per batch row
__device__ unsigned int g_cnt[B];    // tickets (last arriver resets to 0)

// 256-bit global load (sm_100+): 32B/lane, 8 full 128B lines per warp-instr.
// Carries the L2 evict-last retention hint (legal only on .v8.b32 per ptxas).
__device__ __forceinline__ void ldg256_keep(const float* p, uint32_t* v) {
    asm volatile(
        "ld.global.nc.L2::evict_last.v8.b32 {%0,%1,%2,%3,%4,%5,%6,%7}, [%8];"
        : "=r"(v[0]), "=r"(v[1]), "=r"(v[2]), "=r"(v[3]),
          "=r"(v[4]), "=r"(v[5]), "=r"(v[6]), "=r"(v[7])
        : "l"(p));
}

// proj v7: persistent streaming, 4 blocks/SM. Lane = (half = l>>4, c = l&15):
// 16 lanes x 32B = one 512B row; warp covers 2 rows per LDG.256. Per
// iteration: 4 front-batched 256-bit loads = 8 rows (4KB), half the load
// instructions and 2x the bytes-in-flight per load slot vs the 128-bit form.
__global__ void __launch_bounds__(256, 4) proj_kernel(const float* __restrict__ emb,
                                                      const float* __restrict__ fc_w) {
    const int lane = threadIdx.x & 31;
    const int warp = threadIdx.x >> 5;
    const int c    = lane & 15;       // 32B chunk within the 512B row
    const int half = lane >> 4;       // row within pair
    const int gw   = blockIdx.x * 8 + warp;

    // my 8 fc_w floats: [c*8, c*8+8)  (512B table, L1-hot)
    const float4* wp = reinterpret_cast<const float4*>(fc_w);
    const float4 wa = wp[c * 2 + 0];
    const float4 wb = wp[c * 2 + 1];

    for (int g = gw; g < NJOBS; g += NWARPS) {
        const int base = g * 8;
        // float offset of (row, chunk c) = row*128 + c*8
        const float* p0 = emb + (unsigned)(base + 0 + half) * 128u + c * 8u;
        const float* p1 = emb + (unsigned)(base + 2 + half) * 128u + c * 8u;
        const float* p2 = emb + (unsigned)(base + 4 + half) * 128u + c * 8u;
        const float* p3 = emb + (unsigned)(base + 6 + half) * 128u + c * 8u;

        uint32_t v0[8], v1[8], v2[8], v3[8];
        ldg256_keep(p0, v0);
        ldg256_keep(p1, v1);
        ldg256_keep(p2, v2);
        ldg256_keep(p3, v3);

        float s0 = 0.f, s1 = 0.f, s2 = 0.f, s3 = 0.f;
        s0 = fmaf(__uint_as_float(v0[0]), wa.x, s0); s0 = fmaf(__uint_as_float(v0[1]), wa.y, s0);
        s0 = fmaf(__uint_as_float(v0[2]), wa.z, s0); s0 = fmaf(__uint_as_float(v0[3]), wa.w, s0);
        s0 = fmaf(__uint_as_float(v0[4]), wb.x, s0); s0 = fmaf(__uint_as_float(v0[5]), wb.y, s0);
        s0 = fmaf(__uint_as_float(v0[6]), wb.z, s0); s0 = fmaf(__uint_as_float(v0[7]), wb.w, s0);
        s1 = fmaf(__uint_as_float(v1[0]), wa.x, s1); s1 = fmaf(__uint_as_float(v1[1]), wa.y, s1);
        s1 = fmaf(__uint_as_float(v1[2]), wa.z, s1); s1 = fmaf(__uint_as_float(v1[3]), wa.w, s1);
        s1 = fmaf(__uint_as_float(v1[4]), wb.x, s1); s1 = fmaf(__uint_as_float(v1[5]), wb.y, s1);
        s1 = fmaf(__uint_as_float(v1[6]), wb.z, s1); s1 = fmaf(__uint_as_float(v1[7]), wb.w, s1);
        s2 = fmaf(__uint_as_float(v2[0]), wa.x, s2); s2 = fmaf(__uint_as_float(v2[1]), wa.y, s2);
        s2 = fmaf(__uint_as_float(v2[2]), wa.z, s2); s2 = fmaf(__uint_as_float(v2[3]), wa.w, s2);
        s2 = fmaf(__uint_as_float(v2[4]), wb.x, s2); s2 = fmaf(__uint_as_float(v2[5]), wb.y, s2);
        s2 = fmaf(__uint_as_float(v2[6]), wb.z, s2); s2 = fmaf(__uint_as_float(v2[7]), wb.w, s2);
        s3 = fmaf(__uint_as_float(v3[0]), wa.x, s3); s3 = fmaf(__uint_as_float(v3[1]), wa.y, s3);
        s3 = fmaf(__uint_as_float(v3[2]), wa.z, s3); s3 = fmaf(__uint_as_float(v3[3]), wa.w, s3);
        s3 = fmaf(__uint_as_float(v3[4]), wb.x, s3); s3 = fmaf(__uint_as_float(v3[5]), wb.y, s3);
        s3 = fmaf(__uint_as_float(v3[6]), wb.z, s3); s3 = fmaf(__uint_as_float(v3[7]), wb.w, s3);

        // reduce each value over the 16 c-lanes sharing its row
        #pragma unroll
        for (int off = 1; off <= 8; off <<= 1) {
            s0 += __shfl_xor_sync(0xffffffffu, s0, off);
            s1 += __shfl_xor_sync(0xffffffffu, s1, off);
            s2 += __shfl_xor_sync(0xffffffffu, s2, off);
            s3 += __shfl_xor_sync(0xffffffffu, s3, off);
        }

        if (c == 0) {   // lanes 0 (half=0) and 16 (half=1) write 4 rows each
            g_proj[base + 0 + half] = s0;
            g_proj[base + 2 + half] = s1;
            g_proj[base + 4 + half] = s2;
            g_proj[base + 6 + half] = s3;
        }
    }
}

// pool: 512 blocks x 256 thr; block (b = bid>>1, h = bid&1) handles tokens
// [h*1024, h*1024+1024): one int4 (4 tokens) per thread, single gather round.
// Ticket finalize: last of the 2 blocks for row b combines partials, writes
// out[b], resets the ticket (device globals start 0 -> replay-deterministic).
__global__ void __launch_bounds__(256) pool_kernel(const int* __restrict__ text,
                                                   const int* __restrict__ lengths,
                                                   const float* __restrict__ fc_b,
                                                   float* __restrict__ out) {
    __shared__ float sred[8];
    const int bid = blockIdx.x;
    const int b   = bid >> 1;
    const int h   = bid & 1;
    const int tid = threadIdx.x;
    const int len = lengths[b];

    const int base = h * 1024;
    int4 t = reinterpret_cast<const int4*>(text + (size_t)b * S + base)[tid];
    const int s = base + tid * 4;

    float acc = 0.0f;
    if (s + 0 < len) acc += g_proj[t.x];
    if (s + 1 < len) acc += g_proj[t.y];
    if (s + 2 < len) acc += g_proj[t.z];
    if (s + 3 < len) acc += g_proj[t.w];

    #pragma unroll
    for (int off = 16; off; off >>= 1)
        acc += __shfl_xor_sync(0xffffffffu, acc, off);
    const int lane = tid & 31, warp = tid >> 5;
    if (lane == 0) sred[warp] = acc;
    __syncthreads();

    if (tid == 0) {
        float part = sred[0] + sred[1] + sred[2] + sred[3]
                   + sred[4] + sred[5] + sred[6] + sred[7];
        g_part[bid] = part;
        __threadfence();
        unsigned int old = atomicAdd(&g_cnt[b], 1u);
        if (old == 1u) {                    // last of the 2 blocks for row b
            __threadfence();
            float v = __ldcg(&g_part[b * 2 + 0]) + __ldcg(&g_part[b * 2 + 1]);
            out[b] = v / (float)len + fc_b[0];
            g_cnt[b] = 0u;                  // re-arm for the next graph replay
        }
    }
}

extern "C" void kernel_launch(void* const* d_in, const int* in_sizes, int n_in,
                              void* d_out, int out_size) {
    const int*   text    = (const int*)d_in[0];
    const int*   lengths = (const int*)d_in[1];
    const float* emb     = (const float*)d_in[2];
    const float* fc_w    = (const float*)d_in[3];
    const float* fc_b    = (const float*)d_in[4];
    float* out = (float*)d_out;

    proj_kernel<<<PBLK, 256>>>(emb, fc_w);
    pool_kernel<<<B * 2, 256>>>(text, lengths, fc_b, out);
}